// round 2
// baseline (speedup 1.0000x reference)
#include <cuda_runtime.h>
#include <cstdint>

// Problem constants
#define NVOX (512*512*48)      // 12,582,912 voxels
#define NROWS (512*512)        // 262,144 (y,x) rows of 48 along k
#define MC 4096                // clusters

// ---------------- device scratch (no allocation allowed) ----------------
__device__ unsigned long long g_mk[NROWS];   // bitmask per row (k-axis packed)
__device__ unsigned long long g_m2[NROWS];   // temp for separable erosion
__device__ unsigned long long g_accA[MC];    // cnt<<40 | sum(c0+256)
__device__ unsigned long long g_accB[MC];    // sum(c2+256)<<32 | sum(c1+256)
__device__ unsigned long long g_keys[MC];    // sort keys
__device__ float g_cx[MC], g_cy[MC];         // centroid xy (original order)
__device__ unsigned g_mat[MC * 128];         // NMS suppression bit-matrix (sorted order)

// ---------------- zero accumulators (split in 2 so k_hist is launch #6) ----
__global__ void k_zeroA() {
    int i = blockIdx.x * blockDim.x + threadIdx.x;
    if (i < MC) g_accA[i] = 0ull;
}
__global__ void k_zeroB() {
    int i = blockIdx.x * blockDim.x + threadIdx.x;
    if (i < MC) g_accB[i] = 0ull;
}

// ---------------- stage 1: build 48-bit masks + erode along k ----------------
__global__ void k_build(const float* __restrict__ prob) {
    int warp = (blockIdx.x * blockDim.x + threadIdx.x) >> 5;
    int lane = threadIdx.x & 31;
    if (warp >= NROWS) return;
    const float* p = prob + (size_t)warp * 48;
    float a = p[lane];
    float b = (lane < 16) ? p[32 + lane] : 0.0f;
    unsigned b0 = __ballot_sync(0xFFFFFFFFu, a > 0.5f);
    unsigned b1 = __ballot_sync(0xFFFFFFFFu, (lane < 16) && (b > 0.5f));
    if (lane == 0) {
        unsigned long long m =
            (unsigned long long)b0 | ((unsigned long long)(b1 & 0xFFFFu) << 32);
        unsigned long long e = m;
        #pragma unroll
        for (int s = 1; s <= 4; s++) e &= (m << s) & (m >> s);
        g_mk[warp] = e;
    }
}

// ---------------- stage 2: erode along x (i1, contiguous rows) ----------------
__global__ void k_erode_y() {
    int r = blockIdx.x * blockDim.x + threadIdx.x;
    if (r >= NROWS) return;
    int i1 = r & 511;
    unsigned long long e = 0ull;
    if (i1 >= 4 && i1 < 508) {
        e = g_mk[r - 4];
        #pragma unroll
        for (int d = -3; d <= 4; d++) e &= g_mk[r + d];
    }
    g_m2[r] = e;
}

// ---------------- stage 3: erode along y (i0, stride-512 rows) ----------------
__global__ void k_erode_x() {
    int r = blockIdx.x * blockDim.x + threadIdx.x;
    if (r >= NROWS) return;
    int i0 = r >> 9;
    unsigned long long e = 0ull;
    if (i0 >= 4 && i0 < 508) {
        e = g_m2[r - 4 * 512];
        #pragma unroll
        for (int d = -3; d <= 4; d++) e &= g_m2[r + d * 512];
    }
    g_mk[r] = e;
}

// ---------------- stage 4: hash + histogram (the heavy pass) ----------------
// 2 packed u64 shared atomics per voxel instead of 4 u32:
//   A = cnt*2^40 + (c0+256)   (fields can't carry; cnt<2^24, biased sums<2^40)
//   B = (c2+256)*2^32 + (c1+256)
// Integer accumulation is EXACT == float32 segment_sum here.
extern __shared__ unsigned long long s_tab64[];
__global__ void __launch_bounds__(1024, 2) k_hist(const float* __restrict__ emb) {
    unsigned long long* sA = s_tab64;
    unsigned long long* sB = s_tab64 + MC;
    for (int t = threadIdx.x; t < 2 * MC; t += blockDim.x) s_tab64[t] = 0ull;
    __syncthreads();

    const float4* e0p = (const float4*)emb;
    const float4* e1p = (const float4*)(emb + NVOX);
    const float4* e2p = (const float4*)(emb + 2 * NVOX);

    int ngroups = NVOX / 4;                 // 4 voxels per group, 12 groups/row
    int stride = gridDim.x * blockDim.x;
    for (int g = blockIdx.x * blockDim.x + threadIdx.x; g < ngroups; g += stride) {
        int row = g / 12;
        int k0 = (g - row * 12) << 2;
        unsigned mm = (unsigned)((g_mk[row] >> k0) & 0xFull);
        if (!mm) continue;
        float4 v0 = __ldg(e0p + g);
        float4 v1 = __ldg(e1p + g);
        float4 v2 = __ldg(e2p + g);
        int idx = g << 2;
        #pragma unroll
        for (int j = 0; j < 4; j++) {
            if (!((mm >> j) & 1u)) continue;
            if (idx + j == NVOX - 1) continue;   // valid[-1] = False
            float e0 = (j == 0) ? v0.x : (j == 1) ? v0.y : (j == 2) ? v0.z : v0.w;
            float e1 = (j == 0) ? v1.x : (j == 1) ? v1.y : (j == 2) ? v1.z : v1.w;
            float e2 = (j == 0) ? v2.x : (j == 1) ? v2.y : (j == 2) ? v2.z : v2.w;
            if (!(e0 > -2.0f || e1 > -2.0f || e2 > -2.0f)) continue;
            float c0 = rintf(e0 * 25.0f);
            float c1 = rintf(e1 * 25.0f);
            float c2 = rintf(e2 * 25.0f);
            unsigned q0 = (unsigned)fminf(fmaxf(c0 + 128.0f, 0.0f), 255.0f);
            unsigned q1 = (unsigned)fminf(fmaxf(c1 + 128.0f, 0.0f), 255.0f);
            unsigned q2 = (unsigned)fminf(fmaxf(c2 + 128.0f, 0.0f), 255.0f);
            unsigned h = q0 * 73856093u ^ q1 * 19349663u ^ q2 * 83492791u;
            int seg = (int)(h & 4095u);
            long long i0 = (long long)c0, i1 = (long long)c1, i2 = (long long)c2;
            unsigned long long a = (1ull << 40) | (unsigned long long)(i0 + 256);
            unsigned long long b = ((unsigned long long)(i2 + 256) << 32)
                                 | (unsigned long long)(i1 + 256);
            atomicAdd(&sA[seg], a);
            atomicAdd(&sB[seg], b);
        }
    }
    __syncthreads();
    for (int t = threadIdx.x; t < MC; t += blockDim.x) {
        unsigned long long a = sA[t];
        if (a) {
            atomicAdd(&g_accA[t], a);
            atomicAdd(&g_accB[t], sB[t]);
        }
    }
}

// ---------------- stage 5: centroids + sort keys ----------------
__global__ void k_fin(float* __restrict__ out) {
    int i = blockIdx.x * blockDim.x + threadIdx.x;
    if (i >= MC) return;
    unsigned long long A = g_accA[i], B = g_accB[i];
    long long cnt = (long long)(A >> 40);
    long long sx = (long long)(A & 0xFFFFFFFFFFull) - 256ll * cnt;
    long long sy = (long long)(B & 0xFFFFFFFFull)   - 256ll * cnt;
    long long sz = (long long)(B >> 32)             - 256ll * cnt;
    float d = fmaxf((float)cnt, 1.0f);
    float cx = (float)sx / d;
    float cy = (float)sy / d;
    float cz = (float)sz / d;
    out[i * 3 + 0] = cx;
    out[i * 3 + 1] = cy;
    out[i * 3 + 2] = cz;
    g_cx[i] = cx;
    g_cy[i] = cy;
    // key: (score+1) << 13 | (4095 - i) -> descending sort == stable argsort(-scores)
    long long scorep1 = (cnt >= 10) ? cnt + 1 : 0ll;
    g_keys[i] = ((unsigned long long)scorep1 << 13) | (unsigned)(4095 - i);
}

// ---------------- stage 6: bitonic sort of 4096 keys (descending) ----------
__global__ void k_sort() {
    __shared__ unsigned long long sk[MC];
    int tid = threadIdx.x;
    for (int t = tid; t < MC; t += 1024) sk[t] = ~g_keys[t];  // ascending on complement
    __syncthreads();
    for (int k = 2; k <= MC; k <<= 1) {
        for (int j = k >> 1; j > 0; j >>= 1) {
            for (int t = tid; t < MC / 2; t += 1024) {
                int i = ((t & ~(j - 1)) << 1) | (t & (j - 1));
                int p = i | j;
                bool up = ((i & k) == 0);
                unsigned long long a = sk[i], b = sk[p];
                if ((a > b) == up) { sk[i] = b; sk[p] = a; }
            }
            __syncthreads();
        }
    }
    for (int t = tid; t < MC; t += 1024) g_keys[t] = ~sk[t];
}

// ---------------- stage 7: pairwise suppression bit-matrix (sorted order) ---
__global__ void k_mat() {
    int gid = blockIdx.x * blockDim.x + threadIdx.x;   // 4096*4096 threads
    int i = gid >> 12;
    int j = gid & 4095;
    int lane = threadIdx.x & 31;
    // warp-uniform lower-triangle early-out: whole warp has j <= i -> all zero
    if ((j | 31) <= i) {
        if (lane == 0) g_mat[i * 128 + (j >> 5)] = 0u;
        return;
    }
    unsigned long long ki = g_keys[i], kj = g_keys[j];
    int oi = 4095 - (int)(ki & 0x1FFFu);
    int oj = 4095 - (int)(kj & 0x1FFFu);
    float cxi = g_cx[oi], cyi = g_cy[oi];
    float cxj = g_cx[oj], cyj = g_cy[oj];
    float bi0 = cxi - 22.5f, bi1 = cyi - 22.5f, bi2 = cxi + 22.5f, bi3 = cyi + 22.5f;
    float bj0 = cxj - 22.5f, bj1 = cyj - 22.5f, bj2 = cxj + 22.5f, bj3 = cyj + 22.5f;
    float x1 = fmaxf(bi0, bj0), y1 = fmaxf(bi1, bj1);
    float x2 = fminf(bi2, bj2), y2 = fminf(bi3, bj3);
    float inter = fmaxf(x2 - x1, 0.0f) * fmaxf(y2 - y1, 0.0f);
    float a1 = (bi2 - bi0) * (bi3 - bi1);
    float a2 = (bj2 - bj0) * (bj3 - bj1);
    float iou = inter / fmaxf(a1 + a2 - inter, 1e-9f);
    bool sup = (iou > 0.5f) && (j > i);
    unsigned bits = __ballot_sync(0xFFFFFFFFu, sup);
    if (lane == 0) g_mat[i * 128 + (j >> 5)] = bits;
}

// ---------------- stage 8: single-warp greedy NMS scan ----------------
__global__ void k_scan(float* __restrict__ keep_out) {
    __shared__ unsigned sh_rem[128], sh_cand[128], sh_kept[128];
    int lane = threadIdx.x;
    #pragma unroll
    for (int s = 0; s < 4; s++) { sh_rem[s * 32 + lane] = 0u; sh_kept[s * 32 + lane] = 0u; }
    for (int w = 0; w < 128; w++) {
        unsigned long long kk = g_keys[w * 32 + lane];
        unsigned bb = __ballot_sync(0xFFFFFFFFu, (kk >> 13) >= 11ull);  // score >= 10
        if (lane == 0) sh_cand[w] = bb;
    }
    __syncwarp();
    for (int w = 0; w < 128; w++) {
        unsigned cand = sh_cand[w] & ~sh_rem[w];
        while (cand) {
            int b = __ffs(cand) - 1;
            int i = w * 32 + b;
            if (lane == 0) sh_kept[w] |= (1u << b);
            const unsigned* row = g_mat + i * 128;
            sh_rem[lane]      |= row[lane];
            sh_rem[32 + lane] |= row[32 + lane];
            sh_rem[64 + lane] |= row[64 + lane];
            sh_rem[96 + lane] |= row[96 + lane];
            __syncwarp();
            cand &= ~(1u << b);
            cand &= ~sh_rem[w];
        }
    }
    __syncwarp();
    if (keep_out) {
        for (int w = 0; w < 128; w++) {
            unsigned long long kk = g_keys[w * 32 + lane];
            int orig = 4095 - (int)(kk & 0x1FFFu);
            keep_out[orig] = ((sh_kept[w] >> lane) & 1u) ? 1.0f : 0.0f;
        }
    }
}

// ---------------- launch ----------------
extern "C" void kernel_launch(void* const* d_in, const int* in_sizes, int n_in,
                              void* d_out, int out_size) {
    const float* emb  = (const float*)d_in[0];
    const float* prob = (const float*)d_in[1];
    float* out = (float*)d_out;

    k_zeroA<<<(MC + 255) / 256, 256>>>();                  // launch 1
    k_zeroB<<<(MC + 255) / 256, 256>>>();                  // launch 2
    k_build<<<(NROWS * 32) / 256, 256>>>(prob);            // launch 3
    k_erode_y<<<NROWS / 256, 256>>>();                     // launch 4
    k_erode_x<<<NROWS / 256, 256>>>();                     // launch 5

    cudaFuncSetAttribute(k_hist, cudaFuncAttributeMaxDynamicSharedMemorySize, 2 * MC * 8);
    k_hist<<<296, 1024, 2 * MC * 8>>>(emb);                // launch 6 (ncu -s 5 target)

    k_fin<<<MC / 256, 256>>>(out);
    k_sort<<<1, 1024>>>();
    k_mat<<<(MC * MC) / 256, 256>>>();

    float* keep_out = (out_size >= MC * 3 + MC) ? (out + MC * 3) : nullptr;
    k_scan<<<1, 32>>>(keep_out);
}

// round 4
// speedup vs baseline: 1.1341x; 1.1341x over previous
#include <cuda_runtime.h>
#include <cstdint>

// Problem constants
#define NVOX (512*512*48)      // 12,582,912 voxels
#define NROWS (512*512)        // 262,144 (y,x) rows of 48 along k
#define MC 4096                // clusters

// ---------------- device scratch (no allocation allowed) ----------------
__device__ unsigned long long g_mk[NROWS];   // bitmask per row (k-axis packed)
__device__ unsigned long long g_m2[NROWS];   // temp for separable erosion
__device__ unsigned long long g_accA[MC];    // cnt<<40 | sum(c0+256)
__device__ unsigned long long g_accB[MC];    // sum(c2+256)<<32 | sum(c1+256)
__device__ unsigned long long g_keys[MC];    // sort keys
__device__ float g_cx[MC], g_cy[MC];         // centroid xy (original order)
__device__ unsigned g_mat[MC * 128];         // NMS suppression bit-matrix (sorted order)

// ---------------- zero accumulators (split in 2 so k_hist is launch #6) ----
__global__ void k_zeroA() {
    int i = blockIdx.x * blockDim.x + threadIdx.x;
    if (i < MC) g_accA[i] = 0ull;
}
__global__ void k_zeroB() {
    int i = blockIdx.x * blockDim.x + threadIdx.x;
    if (i < MC) g_accB[i] = 0ull;
}

// ---------------- stage 1: build 48-bit masks + erode along k ----------------
__global__ void k_build(const float* __restrict__ prob) {
    int warp = (blockIdx.x * blockDim.x + threadIdx.x) >> 5;
    int lane = threadIdx.x & 31;
    if (warp >= NROWS) return;
    const float* p = prob + (size_t)warp * 48;
    float a = p[lane];
    float b = (lane < 16) ? p[32 + lane] : 0.0f;
    unsigned b0 = __ballot_sync(0xFFFFFFFFu, a > 0.5f);
    unsigned b1 = __ballot_sync(0xFFFFFFFFu, (lane < 16) && (b > 0.5f));
    if (lane == 0) {
        unsigned long long m =
            (unsigned long long)b0 | ((unsigned long long)(b1 & 0xFFFFu) << 32);
        unsigned long long e = m;
        #pragma unroll
        for (int s = 1; s <= 4; s++) e &= (m << s) & (m >> s);
        g_mk[warp] = e;
    }
}

// ---------------- stage 2: erode along x (i1, contiguous rows) ----------------
__global__ void k_erode_y() {
    int r = blockIdx.x * blockDim.x + threadIdx.x;
    if (r >= NROWS) return;
    int i1 = r & 511;
    unsigned long long e = 0ull;
    if (i1 >= 4 && i1 < 508) {
        e = g_mk[r - 4];
        #pragma unroll
        for (int d = -3; d <= 4; d++) e &= g_mk[r + d];
    }
    g_m2[r] = e;
}

// ---------------- stage 3: erode along y (i0, stride-512 rows) ----------------
__global__ void k_erode_x() {
    int r = blockIdx.x * blockDim.x + threadIdx.x;
    if (r >= NROWS) return;
    int i0 = r >> 9;
    unsigned long long e = 0ull;
    if (i0 >= 4 && i0 < 508) {
        e = g_m2[r - 4 * 512];
        #pragma unroll
        for (int d = -3; d <= 4; d++) e &= g_m2[r + d * 512];
    }
    g_mk[r] = e;
}

// ---------------- stage 4: hash + histogram (the heavy pass) ----------------
// ONE packed u64 shared atomic per voxel (halves ATOMS bank traffic vs 2xu64):
//   v = cnt<<51 | (c2+256)<<34 | (c1+256)<<17 | (c0+256)
// Carry-safe while per-(block,seg) cnt <= 255 (sums <= 255*511 < 2^17);
// per-block seg occupancy is ~Poisson(10), so this holds with huge margin.
// Integer accumulation is EXACT == float32 segment_sum here.
extern __shared__ unsigned long long s_tab64[];
__global__ void __launch_bounds__(1024, 2) k_hist(const float* __restrict__ emb) {
    unsigned long long* sP = s_tab64;
    for (int t = threadIdx.x; t < MC; t += blockDim.x) sP[t] = 0ull;
    __syncthreads();

    const float4* e0p = (const float4*)emb;
    const float4* e1p = (const float4*)(emb + NVOX);
    const float4* e2p = (const float4*)(emb + 2 * NVOX);

    int ngroups = NVOX / 4;                 // 4 voxels per group, 12 groups/row
    int stride = gridDim.x * blockDim.x;
    for (int g = blockIdx.x * blockDim.x + threadIdx.x; g < ngroups; g += stride) {
        int row = g / 12;
        int k0 = (g - row * 12) << 2;
        unsigned mm = (unsigned)((g_mk[row] >> k0) & 0xFull);
        if (!mm) continue;
        float4 v0 = __ldg(e0p + g);
        float4 v1 = __ldg(e1p + g);
        float4 v2 = __ldg(e2p + g);
        #pragma unroll
        for (int j = 0; j < 4; j++) {
            if (!((mm >> j) & 1u)) continue;
            // NOTE: idx == NVOX-1 has k=47, always eroded -> no explicit check needed
            float e0 = (j == 0) ? v0.x : (j == 1) ? v0.y : (j == 2) ? v0.z : v0.w;
            float e1 = (j == 0) ? v1.x : (j == 1) ? v1.y : (j == 2) ? v1.z : v1.w;
            float e2 = (j == 0) ? v2.x : (j == 1) ? v2.y : (j == 2) ? v2.z : v2.w;
            if (!(e0 > -2.0f || e1 > -2.0f || e2 > -2.0f)) continue;
            float c0 = rintf(e0 * 25.0f);
            float c1 = rintf(e1 * 25.0f);
            float c2 = rintf(e2 * 25.0f);
            unsigned q0 = (unsigned)fminf(fmaxf(c0 + 128.0f, 0.0f), 255.0f);
            unsigned q1 = (unsigned)fminf(fmaxf(c1 + 128.0f, 0.0f), 255.0f);
            unsigned q2 = (unsigned)fminf(fmaxf(c2 + 128.0f, 0.0f), 255.0f);
            unsigned h = q0 * 73856093u ^ q1 * 19349663u ^ q2 * 83492791u;
            int seg = (int)(h & 4095u);
            long long i0 = (long long)c0, i1 = (long long)c1, i2 = (long long)c2;
            unsigned long long v = (1ull << 51)
                                 | ((unsigned long long)(i2 + 256) << 34)
                                 | ((unsigned long long)(i1 + 256) << 17)
                                 |  (unsigned long long)(i0 + 256);
            atomicAdd(&sP[seg], v);
        }
    }
    __syncthreads();
    for (int t = threadIdx.x; t < MC; t += blockDim.x) {
        unsigned long long v = sP[t];
        if (v) {
            unsigned long long cnt = v >> 51;
            unsigned long long s0 = v & 0x1FFFFull;
            unsigned long long s1 = (v >> 17) & 0x1FFFFull;
            unsigned long long s2 = (v >> 34) & 0x1FFFFull;
            atomicAdd(&g_accA[t], (cnt << 40) | s0);
            atomicAdd(&g_accB[t], (s2 << 32) | s1);
        }
    }
}

// ---------------- stage 5: centroids + sort keys ----------------
__global__ void k_fin(float* __restrict__ out) {
    int i = blockIdx.x * blockDim.x + threadIdx.x;
    if (i >= MC) return;
    unsigned long long A = g_accA[i], B = g_accB[i];
    long long cnt = (long long)(A >> 40);
    long long sx = (long long)(A & 0xFFFFFFFFFFull) - 256ll * cnt;
    long long sy = (long long)(B & 0xFFFFFFFFull)   - 256ll * cnt;
    long long sz = (long long)(B >> 32)             - 256ll * cnt;
    float d = fmaxf((float)cnt, 1.0f);
    float cx = (float)sx / d;
    float cy = (float)sy / d;
    float cz = (float)sz / d;
    out[i * 3 + 0] = cx;
    out[i * 3 + 1] = cy;
    out[i * 3 + 2] = cz;
    g_cx[i] = cx;
    g_cy[i] = cy;
    // key: (score+1) << 13 | (4095 - i) -> descending sort == stable argsort(-scores)
    long long scorep1 = (cnt >= 10) ? cnt + 1 : 0ll;
    g_keys[i] = ((unsigned long long)scorep1 << 13) | (unsigned)(4095 - i);
}

// ---------------- stage 6: bitonic sort of 4096 keys (descending) ----------
__global__ void k_sort() {
    __shared__ unsigned long long sk[MC];
    int tid = threadIdx.x;
    for (int t = tid; t < MC; t += 1024) sk[t] = ~g_keys[t];  // ascending on complement
    __syncthreads();
    for (int k = 2; k <= MC; k <<= 1) {
        for (int j = k >> 1; j > 0; j >>= 1) {
            for (int t = tid; t < MC / 2; t += 1024) {
                int i = ((t & ~(j - 1)) << 1) | (t & (j - 1));
                int p = i | j;
                bool up = ((i & k) == 0);
                unsigned long long a = sk[i], b = sk[p];
                if ((a > b) == up) { sk[i] = b; sk[p] = a; }
            }
            __syncthreads();
        }
    }
    for (int t = tid; t < MC; t += 1024) g_keys[t] = ~sk[t];
}

// ---------------- stage 7: pairwise suppression bit-matrix (sorted order) ---
__global__ void k_mat() {
    int gid = blockIdx.x * blockDim.x + threadIdx.x;   // 4096*4096 threads
    int i = gid >> 12;
    int j = gid & 4095;
    int lane = threadIdx.x & 31;
    // warp-uniform lower-triangle early-out: whole warp has j <= i -> all zero
    if ((j | 31) <= i) {
        if (lane == 0) g_mat[i * 128 + (j >> 5)] = 0u;
        return;
    }
    unsigned long long ki = g_keys[i], kj = g_keys[j];
    int oi = 4095 - (int)(ki & 0x1FFFu);
    int oj = 4095 - (int)(kj & 0x1FFFu);
    float cxi = g_cx[oi], cyi = g_cy[oi];
    float cxj = g_cx[oj], cyj = g_cy[oj];
    float bi0 = cxi - 22.5f, bi1 = cyi - 22.5f, bi2 = cxi + 22.5f, bi3 = cyi + 22.5f;
    float bj0 = cxj - 22.5f, bj1 = cyj - 22.5f, bj2 = cxj + 22.5f, bj3 = cyj + 22.5f;
    float x1 = fmaxf(bi0, bj0), y1 = fmaxf(bi1, bj1);
    float x2 = fminf(bi2, bj2), y2 = fminf(bi3, bj3);
    float inter = fmaxf(x2 - x1, 0.0f) * fmaxf(y2 - y1, 0.0f);
    float a1 = (bi2 - bi0) * (bi3 - bi1);
    float a2 = (bj2 - bj0) * (bj3 - bj1);
    float iou = inter / fmaxf(a1 + a2 - inter, 1e-9f);
    bool sup = (iou > 0.5f) && (j > i);
    unsigned bits = __ballot_sync(0xFFFFFFFFu, sup);
    if (lane == 0) g_mat[i * 128 + (j >> 5)] = bits;
}

// ---------------- stage 8: single-warp greedy NMS scan ----------------
__global__ void k_scan(float* __restrict__ keep_out) {
    __shared__ unsigned sh_rem[128], sh_cand[128], sh_kept[128];
    int lane = threadIdx.x;
    #pragma unroll
    for (int s = 0; s < 4; s++) { sh_rem[s * 32 + lane] = 0u; sh_kept[s * 32 + lane] = 0u; }
    for (int w = 0; w < 128; w++) {
        unsigned long long kk = g_keys[w * 32 + lane];
        unsigned bb = __ballot_sync(0xFFFFFFFFu, (kk >> 13) >= 11ull);  // score >= 10
        if (lane == 0) sh_cand[w] = bb;
    }
    __syncwarp();
    for (int w = 0; w < 128; w++) {
        unsigned cand = sh_cand[w] & ~sh_rem[w];
        while (cand) {
            int b = __ffs(cand) - 1;
            int i = w * 32 + b;
            if (lane == 0) sh_kept[w] |= (1u << b);
            const unsigned* row = g_mat + i * 128;
            sh_rem[lane]      |= row[lane];
            sh_rem[32 + lane] |= row[32 + lane];
            sh_rem[64 + lane] |= row[64 + lane];
            sh_rem[96 + lane] |= row[96 + lane];
            __syncwarp();
            cand &= ~(1u << b);
            cand &= ~sh_rem[w];
        }
    }
    __syncwarp();
    if (keep_out) {
        for (int w = 0; w < 128; w++) {
            unsigned long long kk = g_keys[w * 32 + lane];
            int orig = 4095 - (int)(kk & 0x1FFFu);
            keep_out[orig] = ((sh_kept[w] >> lane) & 1u) ? 1.0f : 0.0f;
        }
    }
}

// ---------------- launch ----------------
extern "C" void kernel_launch(void* const* d_in, const int* in_sizes, int n_in,
                              void* d_out, int out_size) {
    const float* emb  = (const float*)d_in[0];
    const float* prob = (const float*)d_in[1];
    float* out = (float*)d_out;

    k_zeroA<<<(MC + 255) / 256, 256>>>();                  // launch 1
    k_zeroB<<<(MC + 255) / 256, 256>>>();                  // launch 2
    k_build<<<(NROWS * 32) / 256, 256>>>(prob);            // launch 3
    k_erode_y<<<NROWS / 256, 256>>>();                     // launch 4
    k_erode_x<<<NROWS / 256, 256>>>();                     // launch 5

    cudaFuncSetAttribute(k_hist, cudaFuncAttributeMaxDynamicSharedMemorySize, MC * 8);
    k_hist<<<296, 1024, MC * 8>>>(emb);                    // launch 6 (ncu -s 5 target)

    k_fin<<<MC / 256, 256>>>(out);
    k_sort<<<1, 1024>>>();
    k_mat<<<(MC * MC) / 256, 256>>>();

    float* keep_out = (out_size >= MC * 3 + MC) ? (out + MC * 3) : nullptr;
    k_scan<<<1, 32>>>(keep_out);
}

// round 5
// speedup vs baseline: 2.0211x; 1.7820x over previous
#include <cuda_runtime.h>
#include <cstdint>

// Problem constants
#define NVOX (512*512*48)      // 12,582,912 voxels
#define NROWS (512*512)        // 262,144 (y,x) rows of 48 along k
#define MC 4096                // clusters

// ---------------- device scratch (no allocation allowed) ----------------
__device__ unsigned long long g_mk[NROWS];   // bitmask per row (k-axis packed)
__device__ unsigned long long g_m2[NROWS];   // temp for separable erosion
__device__ unsigned long long g_accA[MC];    // cnt<<40 | sum(c0+256)
__device__ unsigned long long g_accB[MC];    // sum(c2+256)<<32 | sum(c1+256)
__device__ unsigned long long g_keys[MC];    // (cnt+1)<<13 | (4095-i)  (0 if not cluster)
__device__ float g_cx[MC], g_cy[MC];         // centroid xy (original order)

// ---------------- stage 1: masks + k-erosion (+ fused accumulator zeroing) --
__global__ void k_build(const float* __restrict__ prob) {
    int gid = blockIdx.x * blockDim.x + threadIdx.x;
    if (gid < MC) { g_accA[gid] = 0ull; g_accB[gid] = 0ull; }   // fused zeroing
    int warp = gid >> 5;
    int lane = threadIdx.x & 31;
    if (warp >= NROWS) return;
    const float* p = prob + (size_t)warp * 48;
    float a = p[lane];
    float b = (lane < 16) ? p[32 + lane] : 0.0f;
    unsigned b0 = __ballot_sync(0xFFFFFFFFu, a > 0.5f);
    unsigned b1 = __ballot_sync(0xFFFFFFFFu, (lane < 16) && (b > 0.5f));
    if (lane == 0) {
        unsigned long long m =
            (unsigned long long)b0 | ((unsigned long long)(b1 & 0xFFFFu) << 32);
        unsigned long long e = m;
        #pragma unroll
        for (int s = 1; s <= 4; s++) e &= (m << s) & (m >> s);
        g_mk[warp] = e;
    }
}

// ---------------- stage 2: erode along x (i1, contiguous rows) --------------
__global__ void k_erode_y() {
    int r = blockIdx.x * blockDim.x + threadIdx.x;
    if (r >= NROWS) return;
    int i1 = r & 511;
    unsigned long long e = 0ull;
    if (i1 >= 4 && i1 < 508) {
        e = g_mk[r - 4];
        #pragma unroll
        for (int d = -3; d <= 4; d++) e &= g_mk[r + d];
    }
    g_m2[r] = e;
}

// ---------------- stage 3: erode along y (i0, stride-512 rows) --------------
__global__ void k_erode_x() {
    int r = blockIdx.x * blockDim.x + threadIdx.x;
    if (r >= NROWS) return;
    int i0 = r >> 9;
    unsigned long long e = 0ull;
    if (i0 >= 4 && i0 < 508) {
        e = g_m2[r - 4 * 512];
        #pragma unroll
        for (int d = -3; d <= 4; d++) e &= g_m2[r + d * 512];
    }
    g_mk[r] = e;
}

// ---------------- stage 4: hash + histogram (launch #4 -> ncu captures it) --
// ONE packed u64 shared atomic per voxel:
//   v = cnt<<51 | (c2+256)<<34 | (c1+256)<<17 | (c0+256)
// Carry-safe while per-(block,seg) cnt <= 255; occupancy is ~Poisson(10).
// Integer accumulation is EXACT == float32 segment_sum here.
extern __shared__ unsigned long long s_tab64[];
__global__ void __launch_bounds__(1024, 2) k_hist(const float* __restrict__ emb) {
    unsigned long long* sP = s_tab64;
    for (int t = threadIdx.x; t < MC; t += blockDim.x) sP[t] = 0ull;
    __syncthreads();

    const float4* e0p = (const float4*)emb;
    const float4* e1p = (const float4*)(emb + NVOX);
    const float4* e2p = (const float4*)(emb + 2 * NVOX);

    int ngroups = NVOX / 4;                 // 4 voxels per group, 12 groups/row
    int stride = gridDim.x * blockDim.x;
    for (int g = blockIdx.x * blockDim.x + threadIdx.x; g < ngroups; g += stride) {
        int row = g / 12;
        int k0 = (g - row * 12) << 2;
        unsigned mm = (unsigned)((g_mk[row] >> k0) & 0xFull);
        if (!mm) continue;
        float4 v0 = __ldg(e0p + g);
        float4 v1 = __ldg(e1p + g);
        float4 v2 = __ldg(e2p + g);
        #pragma unroll
        for (int j = 0; j < 4; j++) {
            if (!((mm >> j) & 1u)) continue;
            // idx == NVOX-1 has k=47, always eroded -> no explicit check needed
            float e0 = (j == 0) ? v0.x : (j == 1) ? v0.y : (j == 2) ? v0.z : v0.w;
            float e1 = (j == 0) ? v1.x : (j == 1) ? v1.y : (j == 2) ? v1.z : v1.w;
            float e2 = (j == 0) ? v2.x : (j == 1) ? v2.y : (j == 2) ? v2.z : v2.w;
            if (!(e0 > -2.0f || e1 > -2.0f || e2 > -2.0f)) continue;
            float c0 = rintf(e0 * 25.0f);
            float c1 = rintf(e1 * 25.0f);
            float c2 = rintf(e2 * 25.0f);
            unsigned q0 = (unsigned)fminf(fmaxf(c0 + 128.0f, 0.0f), 255.0f);
            unsigned q1 = (unsigned)fminf(fmaxf(c1 + 128.0f, 0.0f), 255.0f);
            unsigned q2 = (unsigned)fminf(fmaxf(c2 + 128.0f, 0.0f), 255.0f);
            unsigned h = q0 * 73856093u ^ q1 * 19349663u ^ q2 * 83492791u;
            int seg = (int)(h & 4095u);
            long long i0 = (long long)c0, i1 = (long long)c1, i2 = (long long)c2;
            unsigned long long v = (1ull << 51)
                                 | ((unsigned long long)(i2 + 256) << 34)
                                 | ((unsigned long long)(i1 + 256) << 17)
                                 |  (unsigned long long)(i0 + 256);
            atomicAdd(&sP[seg], v);
        }
    }
    __syncthreads();
    for (int t = threadIdx.x; t < MC; t += blockDim.x) {
        unsigned long long v = sP[t];
        if (v) {
            unsigned long long cnt = v >> 51;
            unsigned long long s0 = v & 0x1FFFFull;
            unsigned long long s1 = (v >> 17) & 0x1FFFFull;
            unsigned long long s2 = (v >> 34) & 0x1FFFFull;
            atomicAdd(&g_accA[t], (cnt << 40) | s0);
            atomicAdd(&g_accB[t], (s2 << 32) | s1);
        }
    }
}

// ---------------- stage 5: centroids + priority keys ----------------
__global__ void k_fin(float* __restrict__ out) {
    int i = blockIdx.x * blockDim.x + threadIdx.x;
    if (i >= MC) return;
    unsigned long long A = g_accA[i], B = g_accB[i];
    long long cnt = (long long)(A >> 40);
    long long sx = (long long)(A & 0xFFFFFFFFFFull) - 256ll * cnt;
    long long sy = (long long)(B & 0xFFFFFFFFull)   - 256ll * cnt;
    long long sz = (long long)(B >> 32)             - 256ll * cnt;
    float d = fmaxf((float)cnt, 1.0f);
    float cx = (float)sx / d;
    float cy = (float)sy / d;
    float cz = (float)sz / d;
    out[i * 3 + 0] = cx;
    out[i * 3 + 1] = cy;
    out[i * 3 + 2] = cz;
    g_cx[i] = cx;
    g_cy[i] = cy;
    // priority key: higher = earlier in stable argsort(-counts).
    // Non-cluster (cnt<10) -> key 0 (never a candidate).
    long long scorep1 = (cnt >= 10) ? cnt + 1 : 0ll;
    g_keys[i] = ((unsigned long long)scorep1 << 13) | (unsigned)(4095 - i);
}

// ---------------- stage 6: on-the-fly greedy NMS (argmax iteration) ---------
// Equivalent to the reference's sort + fori_loop: repeatedly take the highest
// -priority remaining candidate (key embeds stable tie-break), keep it, and
// clear all remaining candidates with IoU > 0.5 (all are lower priority).
__global__ void k_nms(float* __restrict__ keep_out) {
    __shared__ unsigned long long skey[MC];
    __shared__ unsigned alive[128];
    __shared__ unsigned long long red[256];
    __shared__ float bb[4];
    int tid = threadIdx.x;
    for (int w = tid; w < 128; w += 256) alive[w] = 0u;
    __syncthreads();
    for (int t = tid; t < MC; t += 256) {
        unsigned long long k = g_keys[t];
        skey[t] = k;
        if (keep_out) keep_out[t] = 0.0f;
        if ((k >> 13) != 0ull) atomicOr(&alive[t >> 5], 1u << (t & 31));
    }
    __syncthreads();

    while (true) {
        // block-wide argmax over alive candidates
        unsigned long long m = 0ull;
        for (int t = tid; t < MC; t += 256)
            if ((alive[t >> 5] >> (t & 31)) & 1u) {
                unsigned long long k = skey[t];
                if (k > m) m = k;
            }
        red[tid] = m;
        __syncthreads();
        #pragma unroll
        for (int s = 128; s > 0; s >>= 1) {
            if (tid < s && red[tid + s] > red[tid]) red[tid] = red[tid + s];
            __syncthreads();
        }
        unsigned long long best = red[0];
        __syncthreads();
        if ((best >> 13) == 0ull) break;            // no candidates left
        int i = 4095 - (int)(best & 0x1FFFu);
        if (tid == 0) {
            if (keep_out) keep_out[i] = 1.0f;
            alive[i >> 5] &= ~(1u << (i & 31));
            float cx = g_cx[i], cy = g_cy[i];
            bb[0] = cx - 22.5f; bb[1] = cy - 22.5f;
            bb[2] = cx + 22.5f; bb[3] = cy + 22.5f;
        }
        __syncthreads();
        float bi0 = bb[0], bi1 = bb[1], bi2 = bb[2], bi3 = bb[3];
        float a1 = (bi2 - bi0) * (bi3 - bi1);
        for (int t = tid; t < MC; t += 256) {
            if (!((alive[t >> 5] >> (t & 31)) & 1u)) continue;
            float cx = g_cx[t], cy = g_cy[t];
            float bj0 = cx - 22.5f, bj1 = cy - 22.5f;
            float bj2 = cx + 22.5f, bj3 = cy + 22.5f;
            float x1 = fmaxf(bi0, bj0), y1 = fmaxf(bi1, bj1);
            float x2 = fminf(bi2, bj2), y2 = fminf(bi3, bj3);
            float inter = fmaxf(x2 - x1, 0.0f) * fmaxf(y2 - y1, 0.0f);
            float a2 = (bj2 - bj0) * (bj3 - bj1);
            float iou = inter / fmaxf(a1 + a2 - inter, 1e-9f);
            if (iou > 0.5f)
                atomicAnd(&alive[t >> 5], ~(1u << (t & 31)));
        }
        __syncthreads();
    }
}

// ---------------- launch ----------------
extern "C" void kernel_launch(void* const* d_in, const int* in_sizes, int n_in,
                              void* d_out, int out_size) {
    const float* emb  = (const float*)d_in[0];
    const float* prob = (const float*)d_in[1];
    float* out = (float*)d_out;

    k_build<<<(NROWS * 32) / 256, 256>>>(prob);            // launch 1 (+ zeroing)
    k_erode_y<<<NROWS / 256, 256>>>();                     // launch 2
    k_erode_x<<<NROWS / 256, 256>>>();                     // launch 3

    cudaFuncSetAttribute(k_hist, cudaFuncAttributeMaxDynamicSharedMemorySize, MC * 8);
    k_hist<<<296, 1024, MC * 8>>>(emb);                    // launch 4 (ncu target)

    k_fin<<<MC / 256, 256>>>(out);                         // launch 5

    float* keep_out = (out_size >= MC * 3 + MC) ? (out + MC * 3) : nullptr;
    k_nms<<<1, 256>>>(keep_out);                           // launch 6
}

// round 8
// speedup vs baseline: 2.0667x; 1.0226x over previous
#include <cuda_runtime.h>
#include <cstdint>

// Problem constants
#define NVOX (512*512*48)      // 12,582,912 voxels
#define NROWS (512*512)        // 262,144 (y,x) rows of 48 along k
#define MC 4096                // clusters

// ---------------- device scratch (no allocation allowed) ----------------
__device__ unsigned long long g_mk[NROWS];   // raw bitmask per row (k-eroded)
__device__ unsigned long long g_m2[NROWS];   // fully eroded mask
__device__ unsigned long long g_accA[MC];    // cnt<<40 | sum(c0+256)
__device__ unsigned long long g_accB[MC];    // sum(c2+256)<<32 | sum(c1+256)

// ---------------- stage 1: masks + k-erosion (+ fused accumulator zeroing) --
__global__ void k_build(const float* __restrict__ prob) {
    int gid = blockIdx.x * blockDim.x + threadIdx.x;
    if (gid < MC) { g_accA[gid] = 0ull; g_accB[gid] = 0ull; }   // fused zeroing
    int warp = gid >> 5;
    int lane = threadIdx.x & 31;
    if (warp >= NROWS) return;
    const float* p = prob + (size_t)warp * 48;
    float a = p[lane];
    float b = (lane < 16) ? p[32 + lane] : 0.0f;
    unsigned b0 = __ballot_sync(0xFFFFFFFFu, a > 0.5f);
    unsigned b1 = __ballot_sync(0xFFFFFFFFu, (lane < 16) && (b > 0.5f));
    if (lane == 0) {
        unsigned long long m =
            (unsigned long long)b0 | ((unsigned long long)(b1 & 0xFFFFu) << 32);
        unsigned long long e = m;
        #pragma unroll
        for (int s = 1; s <= 4; s++) e &= (m << s) & (m >> s);
        g_mk[warp] = e;
    }
}

// ---------------- stage 2: fused x+y erosion, one tiled pass ----------------
// 32x32 tile + 4-halo in shared; zero-fill out-of-range == reference zero-pad.
__global__ void k_erode() {
    __shared__ unsigned long long m[40 * 40];
    __shared__ unsigned long long t[40 * 32];
    int bx = (blockIdx.x & 15) << 5;    // i1 base
    int by = (blockIdx.x >> 4) << 5;    // i0 base
    for (int idx = threadIdx.x; idx < 40 * 40; idx += 256) {
        int ly = idx / 40, lx = idx - ly * 40;
        int gy = by + ly - 4, gx = bx + lx - 4;
        unsigned long long v = 0ull;
        if ((unsigned)gy < 512u && (unsigned)gx < 512u) v = g_mk[gy * 512 + gx];
        m[idx] = v;
    }
    __syncthreads();
    // erode along x: t[ly][lx] covers gx-4..gx+4 for gx = bx+lx
    for (int idx = threadIdx.x; idx < 40 * 32; idx += 256) {
        int ly = idx >> 5, lx = idx & 31;
        unsigned long long e = m[ly * 40 + lx];
        #pragma unroll
        for (int d = 1; d <= 8; d++) e &= m[ly * 40 + lx + d];
        t[idx] = e;
    }
    __syncthreads();
    // erode along y: out gy = by+ly reads t rows ly..ly+8 (gy-4..gy+4)
    for (int idx = threadIdx.x; idx < 32 * 32; idx += 256) {
        int ly = idx >> 5, lx = idx & 31;
        unsigned long long e = t[ly * 32 + lx];
        #pragma unroll
        for (int d = 1; d <= 8; d++) e &= t[(ly + d) * 32 + lx];
        g_m2[(by + ly) * 512 + (bx + lx)] = e;
    }
}

// ---------------- stage 3: hash + histogram (the heavy pass) ----------------
// ONE packed u64 shared atomic per voxel:
//   v = cnt<<51 | (c2+256)<<34 | (c1+256)<<17 | (c0+256)
// Carry-safe while per-(block,seg) cnt <= 255; occupancy is ~Poisson(10).
// Integer accumulation is EXACT == float32 segment_sum here.
// All-integer quantization: __float2int_rn == rintf (RN-even), int clamp
// == float clamp on integer-valued floats.
extern __shared__ unsigned long long s_tab64[];
__global__ void __launch_bounds__(1024, 2) k_hist(const float* __restrict__ emb) {
    unsigned long long* sP = s_tab64;
    for (int t = threadIdx.x; t < MC; t += blockDim.x) sP[t] = 0ull;
    __syncthreads();

    const float4* e0p = (const float4*)emb;
    const float4* e1p = (const float4*)(emb + NVOX);
    const float4* e2p = (const float4*)(emb + 2 * NVOX);

    int ngroups = NVOX / 4;                 // 4 voxels per group, 12 groups/row
    int stride = gridDim.x * blockDim.x;
    for (int g = blockIdx.x * blockDim.x + threadIdx.x; g < ngroups; g += stride) {
        int row = g / 12;
        int k0 = (g - row * 12) << 2;
        unsigned mm = (unsigned)((g_m2[row] >> k0) & 0xFull);
        if (!mm) continue;
        float4 v0 = __ldg(e0p + g);
        float4 v1 = __ldg(e1p + g);
        float4 v2 = __ldg(e2p + g);
        #pragma unroll
        for (int j = 0; j < 4; j++) {
            if (!((mm >> j) & 1u)) continue;
            // idx == NVOX-1 has k=47, always eroded -> no explicit check needed
            float e0 = (j == 0) ? v0.x : (j == 1) ? v0.y : (j == 2) ? v0.z : v0.w;
            float e1 = (j == 0) ? v1.x : (j == 1) ? v1.y : (j == 2) ? v1.z : v1.w;
            float e2 = (j == 0) ? v2.x : (j == 1) ? v2.y : (j == 2) ? v2.z : v2.w;
            if (!(e0 > -2.0f || e1 > -2.0f || e2 > -2.0f)) continue;
            int c0 = __float2int_rn(e0 * 25.0f);
            int c1 = __float2int_rn(e1 * 25.0f);
            int c2 = __float2int_rn(e2 * 25.0f);
            unsigned q0 = (unsigned)min(max(c0 + 128, 0), 255);
            unsigned q1 = (unsigned)min(max(c1 + 128, 0), 255);
            unsigned q2 = (unsigned)min(max(c2 + 128, 0), 255);
            unsigned h = q0 * 73856093u ^ q1 * 19349663u ^ q2 * 83492791u;
            int seg = (int)(h & 4095u);
            unsigned long long v = (1ull << 51)
                                 | ((unsigned long long)(unsigned)(c2 + 256) << 34)
                                 | ((unsigned long long)(unsigned)(c1 + 256) << 17)
                                 |  (unsigned long long)(unsigned)(c0 + 256);
            atomicAdd(&sP[seg], v);
        }
    }
    __syncthreads();
    for (int t = threadIdx.x; t < MC; t += blockDim.x) {
        unsigned long long v = sP[t];
        if (v) {
            unsigned long long cnt = v >> 51;
            unsigned long long s0 = v & 0x1FFFFull;
            unsigned long long s1 = (v >> 17) & 0x1FFFFull;
            unsigned long long s2 = (v >> 34) & 0x1FFFFull;
            atomicAdd(&g_accA[t], (cnt << 40) | s0);
            atomicAdd(&g_accB[t], (s2 << 32) | s1);
        }
    }
}

// ---------------- stage 4: centroids + greedy NMS (fused, single block) -----
// Fin: unpack sums -> centroids (written to out + smem) + priority keys.
// NMS: argmax iteration == reference's sort + fori_loop (key embeds stable
// tie-break; every still-alive candidate is lower priority than the kept box).
__global__ void k_nms(float* __restrict__ out, float* __restrict__ keep_out) {
    extern __shared__ char dyn[];
    float* scx = (float*)dyn;                                  // 4096
    float* scy = scx + MC;                                     // 4096
    unsigned long long* skey = (unsigned long long*)(scy + MC);// 4096
    __shared__ unsigned alive[128];
    __shared__ unsigned long long red[256];
    __shared__ float bb[4];
    int tid = threadIdx.x;
    for (int w = tid; w < 128; w += 256) alive[w] = 0u;
    __syncthreads();
    for (int i = tid; i < MC; i += 256) {
        unsigned long long A = g_accA[i], B = g_accB[i];
        long long cnt = (long long)(A >> 40);
        long long sx = (long long)(A & 0xFFFFFFFFFFull) - 256ll * cnt;
        long long sy = (long long)(B & 0xFFFFFFFFull)   - 256ll * cnt;
        long long sz = (long long)(B >> 32)             - 256ll * cnt;
        float d = fmaxf((float)cnt, 1.0f);
        float cx = (float)sx / d;
        float cy = (float)sy / d;
        out[i * 3 + 0] = cx;
        out[i * 3 + 1] = cy;
        out[i * 3 + 2] = (float)sz / d;
        scx[i] = cx; scy[i] = cy;
        unsigned long long key = (cnt >= 10)
            ? (((unsigned long long)(cnt + 1) << 13) | (unsigned)(4095 - i)) : 0ull;
        skey[i] = key;
        if (keep_out) keep_out[i] = 0.0f;
        if (key) atomicOr(&alive[i >> 5], 1u << (i & 31));
    }
    __syncthreads();

    while (true) {
        unsigned long long m = 0ull;
        for (int t = tid; t < MC; t += 256)
            if ((alive[t >> 5] >> (t & 31)) & 1u) {
                unsigned long long k = skey[t];
                if (k > m) m = k;
            }
        red[tid] = m;
        __syncthreads();
        #pragma unroll
        for (int s = 128; s > 0; s >>= 1) {
            if (tid < s && red[tid + s] > red[tid]) red[tid] = red[tid + s];
            __syncthreads();
        }
        unsigned long long best = red[0];
        __syncthreads();
        if (best == 0ull) break;                 // no candidates left
        int i = 4095 - (int)(best & 0x1FFFu);
        if (tid == 0) {
            if (keep_out) keep_out[i] = 1.0f;
            alive[i >> 5] &= ~(1u << (i & 31));
            float cx = scx[i], cy = scy[i];
            bb[0] = cx - 22.5f; bb[1] = cy - 22.5f;
            bb[2] = cx + 22.5f; bb[3] = cy + 22.5f;
        }
        __syncthreads();
        float bi0 = bb[0], bi1 = bb[1], bi2 = bb[2], bi3 = bb[3];
        float a1 = (bi2 - bi0) * (bi3 - bi1);
        for (int t = tid; t < MC; t += 256) {
            if (!((alive[t >> 5] >> (t & 31)) & 1u)) continue;
            float cx = scx[t], cy = scy[t];
            float bj0 = cx - 22.5f, bj1 = cy - 22.5f;
            float bj2 = cx + 22.5f, bj3 = cy + 22.5f;
            float x1 = fmaxf(bi0, bj0), y1 = fmaxf(bi1, bj1);
            float x2 = fminf(bi2, bj2), y2 = fminf(bi3, bj3);
            float inter = fmaxf(x2 - x1, 0.0f) * fmaxf(y2 - y1, 0.0f);
            float a2 = (bj2 - bj0) * (bj3 - bj1);
            float iou = inter / fmaxf(a1 + a2 - inter, 1e-9f);
            if (iou > 0.5f)
                atomicAnd(&alive[t >> 5], ~(1u << (t & 31)));
        }
        __syncthreads();
    }
}

// ---------------- launch ----------------
extern "C" void kernel_launch(void* const* d_in, const int* in_sizes, int n_in,
                              void* d_out, int out_size) {
    const float* emb  = (const float*)d_in[0];
    const float* prob = (const float*)d_in[1];
    float* out = (float*)d_out;

    k_build<<<(NROWS * 32) / 256, 256>>>(prob);            // launch 1 (+ zeroing)
    k_erode<<<256, 256>>>();                               // launch 2 (fused x+y)

    cudaFuncSetAttribute(k_hist, cudaFuncAttributeMaxDynamicSharedMemorySize, MC * 8);
    k_hist<<<296, 1024, MC * 8>>>(emb);                    // launch 3

    float* keep_out = (out_size >= MC * 3 + MC) ? (out + MC * 3) : nullptr;
    cudaFuncSetAttribute(k_nms, cudaFuncAttributeMaxDynamicSharedMemorySize, MC * 16);
    k_nms<<<1, 256, MC * 16>>>(out, keep_out);             // launch 4
}